// round 1
// baseline (speedup 1.0000x reference)
#include <cuda_runtime.h>
#include <math.h>

#define BB   64
#define NN   4096
#define DD   1024
#define DIN  2048
#define DHID 4096
#define NOUT 1000

// ---- scratch (device globals; no allocation allowed) ----
__device__ float g_xn[BB * DD];        // normalized encoder
__device__ float g_z[BB * NN];         // sparsemax input scores
__device__ int   g_nzidx[BB * NN];     // compacted support indices
__device__ float g_nzw[BB * NN];       // compacted weights
__device__ int   g_nnz[BB];
__device__ float g_memvec[BB * DD];    // weighted memory readout
__device__ float g_h1[BB * DHID];      // hidden activations

// ---------------------------------------------------------------------------
// K0: xn = enc / max(||enc||, 1e-6)   (64 blocks x 256)
// ---------------------------------------------------------------------------
__global__ void k0_norm_enc(const float* __restrict__ enc) {
    int b = blockIdx.x;
    __shared__ float red[256];
    float ssq = 0.f;
    for (int i = threadIdx.x; i < DD; i += 256) {
        float v = enc[b * DD + i];
        ssq = fmaf(v, v, ssq);
    }
    red[threadIdx.x] = ssq;
    __syncthreads();
    for (int s = 128; s > 0; s >>= 1) {
        if (threadIdx.x < s) red[threadIdx.x] += red[threadIdx.x + s];
        __syncthreads();
    }
    float inv = 1.f / fmaxf(sqrtf(red[0]), 1e-6f);
    for (int i = threadIdx.x; i < DD; i += 256)
        g_xn[b * DD + i] = enc[b * DD + i] * inv;
}

// ---------------------------------------------------------------------------
// K1: the 1.07 GB pass. One warp per memory row: fused dot + norm.
//     z[b,n] = dot(xn[b], mem[b,n]) / max(||mem[b,n]||, 1e-6) - 1
//     grid = B*N/8 = 32768 blocks x 256 threads (8 warps/block)
// ---------------------------------------------------------------------------
__global__ void k1_scores(const float* __restrict__ mem) {
    int warp = threadIdx.x >> 5, lane = threadIdx.x & 31;
    int r = blockIdx.x * 8 + warp;        // global row in [0, B*N)
    int b = r >> 12;                      // N = 4096
    const float4* m4 = (const float4*)mem + (size_t)r * (DD / 4);
    const float4* x4 = (const float4*)g_xn + (size_t)b * (DD / 4);
    float dot = 0.f, ssq = 0.f;
#pragma unroll
    for (int i = 0; i < 8; i++) {
        float4 m = m4[lane + i * 32];
        float4 x = x4[lane + i * 32];
        dot = fmaf(m.x, x.x, fmaf(m.y, x.y, fmaf(m.z, x.z, fmaf(m.w, x.w, dot))));
        ssq = fmaf(m.x, m.x, fmaf(m.y, m.y, fmaf(m.z, m.z, fmaf(m.w, m.w, ssq))));
    }
#pragma unroll
    for (int o = 16; o; o >>= 1) {
        dot += __shfl_xor_sync(0xFFFFFFFFu, dot, o);
        ssq += __shfl_xor_sync(0xFFFFFFFFu, ssq, o);
    }
    if (lane == 0)
        g_z[r] = dot / fmaxf(sqrtf(ssq), 1e-6f) - 1.0f;
}

// ---------------------------------------------------------------------------
// K2: sparsemax over N=4096 per batch row via Michelot's algorithm (exact
//     simplex projection threshold, no sort). Then compact support.
//     64 blocks x 512 threads, 8 elems/thread (registers).
// ---------------------------------------------------------------------------
__global__ void k2_sparsemax() {
    int b = blockIdx.x, t = threadIdx.x;
    __shared__ float redS[512];
    __shared__ float redK[512];
    __shared__ int cnt;

    float loc[8];
#pragma unroll
    for (int i = 0; i < 8; i++) loc[i] = g_z[b * NN + t + i * 512];

    // initial tau = (sum - 1)/N
    float s = 0.f;
#pragma unroll
    for (int i = 0; i < 8; i++) s += loc[i];
    redS[t] = s;
    __syncthreads();
    for (int st = 256; st > 0; st >>= 1) {
        if (t < st) redS[t] += redS[t + st];
        __syncthreads();
    }
    float tau = (redS[0] - 1.f) / (float)NN;
    __syncthreads();

    // Michelot: tau <- (sum_{z>tau} z - 1)/count; monotone increasing, finite.
    for (int it = 0; it < 64; it++) {
        float S = 0.f, K = 0.f;
#pragma unroll
        for (int i = 0; i < 8; i++) {
            float v = loc[i];
            if (v > tau) { S += v; K += 1.f; }
        }
        redS[t] = S; redK[t] = K;
        __syncthreads();
        for (int st = 256; st > 0; st >>= 1) {
            if (t < st) { redS[t] += redS[t + st]; redK[t] += redK[t + st]; }
            __syncthreads();
        }
        float tn = (redS[0] - 1.f) / redK[0];
        __syncthreads();
        if (!(tn > tau)) break;   // fixed point reached (uniform decision)
        tau = tn;
    }

    if (t == 0) cnt = 0;
    __syncthreads();
#pragma unroll
    for (int i = 0; i < 8; i++) {
        float w = loc[i] - tau;
        if (w > 0.f) {
            int p = atomicAdd(&cnt, 1);
            g_nzidx[b * NN + p] = t + i * 512;
            g_nzw[b * NN + p] = w;
        }
    }
    __syncthreads();
    if (t == 0) g_nnz[b] = cnt;
}

// ---------------------------------------------------------------------------
// K3: memvec[b,:] = sum over support of w * mem[b,idx,:]
//     64 blocks x 256 threads (one float4 column slot per thread)
// ---------------------------------------------------------------------------
__global__ void k3_weighted_sum(const float* __restrict__ mem) {
    int b = blockIdx.x, t = threadIdx.x;
    int nnz = g_nnz[b];
    const float4* base = (const float4*)mem + (size_t)b * NN * (DD / 4);
    float4 acc = make_float4(0.f, 0.f, 0.f, 0.f);
    for (int i = 0; i < nnz; i++) {
        int idx = g_nzidx[b * NN + i];
        float w = g_nzw[b * NN + i];
        float4 m = base[(size_t)idx * (DD / 4) + t];
        acc.x = fmaf(w, m.x, acc.x);
        acc.y = fmaf(w, m.y, acc.y);
        acc.z = fmaf(w, m.z, acc.z);
        acc.w = fmaf(w, m.w, acc.w);
    }
    ((float4*)g_memvec)[b * (DD / 4) + t] = acc;
}

// ---------------------------------------------------------------------------
// K4: h1 = relu([enc, memvec] @ W1^T + b1)   M=64, K=2048, N=4096
//     grid = 128 blocks x 256 threads; 32 outputs x 64 batches per block
// ---------------------------------------------------------------------------
__global__ void k4_fc1(const float* __restrict__ enc,
                       const float* __restrict__ W1,
                       const float* __restrict__ b1) {
    __shared__ float sh[64][33];   // h tile  [batch][k]
    __shared__ float sw[32][33];   // W1 tile [out][k]
    int t = threadIdx.x;
    int obase = blockIdx.x * 32;
    int ol = t & 31;               // output lane (coalesced stores)
    int bg = t >> 5;               // batch group 0..7

    float acc[8];
#pragma unroll
    for (int j = 0; j < 8; j++) acc[j] = 0.f;

    for (int kc = 0; kc < DIN; kc += 32) {
#pragma unroll
        for (int i = 0; i < 8; i++) {           // 64x32 h tile, 8 elems/thread
            int e = t + i * 256;
            int row = e >> 5, col = e & 31;
            int k = kc + col;
            sh[row][col] = (k < DD) ? enc[row * DD + k]
                                    : g_memvec[row * DD + (k - DD)];
        }
#pragma unroll
        for (int i = 0; i < 4; i++) {           // 32x32 W tile, 4 elems/thread
            int e = t + i * 256;
            int row = e >> 5, col = e & 31;
            sw[row][col] = W1[(size_t)(obase + row) * DIN + kc + col];
        }
        __syncthreads();
#pragma unroll
        for (int kk = 0; kk < 32; kk++) {
            float wv = sw[ol][kk];              // stride-33: conflict-free
#pragma unroll
            for (int j = 0; j < 8; j++)
                acc[j] = fmaf(sh[bg * 8 + j][kk], wv, acc[j]);  // broadcast
        }
        __syncthreads();
    }
    int o = obase + ol;
    float bias = b1[o];
#pragma unroll
    for (int j = 0; j < 8; j++) {
        int bb = bg * 8 + j;
        g_h1[(size_t)bb * DHID + o] = fmaxf(acc[j] + bias, 0.f);
    }
}

// ---------------------------------------------------------------------------
// K5: out = h1 @ W2^T + b2   M=64, K=4096, N=1000
//     grid = 32 blocks x 256 threads (last tile partially masked)
// ---------------------------------------------------------------------------
__global__ void k5_fc2(const float* __restrict__ W2,
                       const float* __restrict__ b2,
                       float* __restrict__ out) {
    __shared__ float sh[64][33];
    __shared__ float sw[32][33];
    int t = threadIdx.x;
    int obase = blockIdx.x * 32;
    int ol = t & 31;
    int bg = t >> 5;

    float acc[8];
#pragma unroll
    for (int j = 0; j < 8; j++) acc[j] = 0.f;

    for (int kc = 0; kc < DHID; kc += 32) {
#pragma unroll
        for (int i = 0; i < 8; i++) {
            int e = t + i * 256;
            int row = e >> 5, col = e & 31;
            sh[row][col] = g_h1[(size_t)row * DHID + kc + col];
        }
#pragma unroll
        for (int i = 0; i < 4; i++) {
            int e = t + i * 256;
            int row = e >> 5, col = e & 31;
            int o = obase + row;
            sw[row][col] = (o < NOUT) ? W2[(size_t)o * DHID + kc + col] : 0.f;
        }
        __syncthreads();
#pragma unroll
        for (int kk = 0; kk < 32; kk++) {
            float wv = sw[ol][kk];
#pragma unroll
            for (int j = 0; j < 8; j++)
                acc[j] = fmaf(sh[bg * 8 + j][kk], wv, acc[j]);
        }
        __syncthreads();
    }
    int o = obase + ol;
    if (o < NOUT) {
        float bias = b2[o];
#pragma unroll
        for (int j = 0; j < 8; j++) {
            int bb = bg * 8 + j;
            out[(size_t)bb * NOUT + o] = acc[j] + bias;
        }
    }
}

// ---------------------------------------------------------------------------
extern "C" void kernel_launch(void* const* d_in, const int* in_sizes, int n_in,
                              void* d_out, int out_size) {
    const float* enc = (const float*)d_in[0];   // [64,1024]
    const float* mem = (const float*)d_in[1];   // [64,4096,1024]
    const float* W1  = (const float*)d_in[2];   // [4096,2048]
    const float* b1  = (const float*)d_in[3];   // [4096]
    const float* W2  = (const float*)d_in[4];   // [1000,4096]
    const float* b2  = (const float*)d_in[5];   // [1000]
    float* out = (float*)d_out;                 // [64,1000]

    k0_norm_enc<<<BB, 256>>>(enc);
    k1_scores<<<(BB * NN) / 8, 256>>>(mem);
    k2_sparsemax<<<BB, 512>>>();
    k3_weighted_sum<<<BB, 256>>>(mem);
    k4_fc1<<<DHID / 32, 256>>>(enc, W1, b1);
    k5_fc2<<<(NOUT + 31) / 32, 256>>>(W2, b2, out);
}

// round 2
// speedup vs baseline: 1.8399x; 1.8399x over previous
#include <cuda_runtime.h>
#include <math.h>

#define BB   64
#define NN   4096
#define DD   1024
#define DIN  2048
#define DHID 4096
#define NOUT 1000

// ---- scratch (device globals; no allocation allowed) ----
__device__ float g_xn[BB * DD];        // normalized encoder
__device__ float g_z[BB * NN];         // sparsemax input scores
__device__ int   g_nzidx[BB * NN];     // compacted support indices
__device__ float g_nzw[BB * NN];       // compacted weights
__device__ int   g_nnz[BB];
__device__ float g_memvec[BB * DD];    // weighted memory readout (atomic acc)
__device__ float g_h1[BB * DHID];      // hidden pre-activations (atomic acc)

// ---------------------------------------------------------------------------
// K0: xn = enc / max(||enc||, 1e-6)   (64 blocks x 256)
// ---------------------------------------------------------------------------
__global__ void k0_norm_enc(const float* __restrict__ enc) {
    int b = blockIdx.x;
    __shared__ float red[256];
    float ssq = 0.f;
    for (int i = threadIdx.x; i < DD; i += 256) {
        float v = enc[b * DD + i];
        ssq = fmaf(v, v, ssq);
    }
    red[threadIdx.x] = ssq;
    __syncthreads();
    for (int s = 128; s > 0; s >>= 1) {
        if (threadIdx.x < s) red[threadIdx.x] += red[threadIdx.x + s];
        __syncthreads();
    }
    float inv = 1.f / fmaxf(sqrtf(red[0]), 1e-6f);
    for (int i = threadIdx.x; i < DD; i += 256)
        g_xn[b * DD + i] = enc[b * DD + i] * inv;
}

// ---------------------------------------------------------------------------
// K1: the 1.07 GB pass. One warp per TWO memory rows (doubled MLP), streaming
//     loads (__ldcs) so the non-reusable 1 GB stream doesn't thrash L2.
//     z[b,n] = dot(xn[b], mem[b,n]) / max(||mem[b,n]||, 1e-6) - 1
//     grid = B*N/16 = 16384 blocks x 256 threads (8 warps, 2 rows each)
// ---------------------------------------------------------------------------
__global__ void k1_scores(const float* __restrict__ mem) {
    int warp = threadIdx.x >> 5, lane = threadIdx.x & 31;
    int r0 = (blockIdx.x * 8 + warp) * 2;     // rows r0, r0+1 (same batch)
    int b = r0 >> 12;                         // N = 4096
    const float4* m0 = (const float4*)mem + (size_t)r0 * (DD / 4);
    const float4* m1 = m0 + (DD / 4);
    const float4* x4 = (const float4*)g_xn + (size_t)b * (DD / 4);
    float d0 = 0.f, s0 = 0.f, d1 = 0.f, s1 = 0.f;
#pragma unroll
    for (int i = 0; i < 8; i++) {
        float4 x = x4[lane + i * 32];
        float4 a = __ldcs(&m0[lane + i * 32]);
        float4 c = __ldcs(&m1[lane + i * 32]);
        d0 = fmaf(a.x, x.x, fmaf(a.y, x.y, fmaf(a.z, x.z, fmaf(a.w, x.w, d0))));
        s0 = fmaf(a.x, a.x, fmaf(a.y, a.y, fmaf(a.z, a.z, fmaf(a.w, a.w, s0))));
        d1 = fmaf(c.x, x.x, fmaf(c.y, x.y, fmaf(c.z, x.z, fmaf(c.w, x.w, d1))));
        s1 = fmaf(c.x, c.x, fmaf(c.y, c.y, fmaf(c.z, c.z, fmaf(c.w, c.w, s1))));
    }
#pragma unroll
    for (int o = 16; o; o >>= 1) {
        d0 += __shfl_xor_sync(0xFFFFFFFFu, d0, o);
        s0 += __shfl_xor_sync(0xFFFFFFFFu, s0, o);
        d1 += __shfl_xor_sync(0xFFFFFFFFu, d1, o);
        s1 += __shfl_xor_sync(0xFFFFFFFFu, s1, o);
    }
    if (lane == 0) {
        g_z[r0]     = d0 / fmaxf(sqrtf(s0), 1e-6f) - 1.0f;
        g_z[r0 + 1] = d1 / fmaxf(sqrtf(s1), 1e-6f) - 1.0f;
    }
}

// ---------------------------------------------------------------------------
// K2: sparsemax via Michelot fixed point (exact, no sort). Warp-shuffle
//     reductions (2 barriers/iter). Also zeroes g_memvec for K3's atomics.
//     64 blocks x 512 threads, 8 elems/thread.
// ---------------------------------------------------------------------------
__global__ void k2_sparsemax() {
    int b = blockIdx.x, t = threadIdx.x;
    int lane = t & 31, w = t >> 5;            // 16 warps
    __shared__ float sS[16], sK[16];
    __shared__ float s_tau;
    __shared__ int cnt;

    float loc[8];
#pragma unroll
    for (int i = 0; i < 8; i++) loc[i] = g_z[b * NN + t + i * 512];

    // zero the memvec accumulator (consumed by K3 atomics)
    for (int i = t; i < DD; i += 512) g_memvec[b * DD + i] = 0.f;

    // initial tau = (sum - 1)/N
    float S = 0.f;
#pragma unroll
    for (int i = 0; i < 8; i++) S += loc[i];
#pragma unroll
    for (int o = 16; o; o >>= 1) S += __shfl_xor_sync(0xFFFFFFFFu, S, o);
    if (lane == 0) sS[w] = S;
    __syncthreads();
    if (t == 0) {
        float s = 0.f;
#pragma unroll
        for (int i = 0; i < 16; i++) s += sS[i];
        s_tau = (s - 1.f) / (float)NN;
    }
    __syncthreads();
    float tau = s_tau;

    // Michelot: tau <- (sum_{z>tau} z - 1)/count; monotone non-decreasing.
    for (int it = 0; it < 48; it++) {
        float s = 0.f, k = 0.f;
#pragma unroll
        for (int i = 0; i < 8; i++) {
            float v = loc[i];
            if (v > tau) { s += v; k += 1.f; }
        }
#pragma unroll
        for (int o = 16; o; o >>= 1) {
            s += __shfl_xor_sync(0xFFFFFFFFu, s, o);
            k += __shfl_xor_sync(0xFFFFFFFFu, k, o);
        }
        if (lane == 0) { sS[w] = s; sK[w] = k; }
        __syncthreads();
        if (t == 0) {
            float ss = 0.f, kk = 0.f;
#pragma unroll
            for (int i = 0; i < 16; i++) { ss += sS[i]; kk += sK[i]; }
            s_tau = (ss - 1.f) / kk;
        }
        __syncthreads();
        float tn = s_tau;
        if (!(tn > tau)) break;   // fixed point (uniform decision via smem)
        tau = tn;
    }

    if (t == 0) cnt = 0;
    __syncthreads();
#pragma unroll
    for (int i = 0; i < 8; i++) {
        float wv = loc[i] - tau;
        if (wv > 0.f) {
            int p = atomicAdd(&cnt, 1);
            g_nzidx[b * NN + p] = t + i * 512;
            g_nzw[b * NN + p] = wv;
        }
    }
    __syncthreads();
    if (t == 0) g_nnz[b] = cnt;
}

// ---------------------------------------------------------------------------
// K3: memvec[b,:] += sum over support slice of w * mem[b,idx,:]
//     grid (64, 16): 16-way split of the support, atomicAdd accumulation.
// ---------------------------------------------------------------------------
__global__ void k3_weighted_sum(const float* __restrict__ mem) {
    int b = blockIdx.x, s = blockIdx.y, t = threadIdx.x;
    int nnz = g_nnz[b];
    const float4* base = (const float4*)mem + (size_t)b * NN * (DD / 4);
    float4 acc = make_float4(0.f, 0.f, 0.f, 0.f);
    for (int i = s; i < nnz; i += 16) {
        int idx = g_nzidx[b * NN + i];
        float w = g_nzw[b * NN + i];
        float4 m = __ldcs(&base[(size_t)idx * (DD / 4) + t]);
        acc.x = fmaf(w, m.x, acc.x);
        acc.y = fmaf(w, m.y, acc.y);
        acc.z = fmaf(w, m.z, acc.z);
        acc.w = fmaf(w, m.w, acc.w);
    }
    float* dst = &g_memvec[b * DD + t * 4];
    atomicAdd(dst + 0, acc.x);
    atomicAdd(dst + 1, acc.y);
    atomicAdd(dst + 2, acc.z);
    atomicAdd(dst + 3, acc.w);
}

// ---------------------------------------------------------------------------
// K4 init: h1[b, o] = b1[o]  (partials atomicAdd on top; relu applied in K5)
// ---------------------------------------------------------------------------
__global__ void k4_init(const float* __restrict__ b1) {
    int i = blockIdx.x * 256 + threadIdx.x;   // BB*DHID / 256 = 1024 blocks
    g_h1[i] = b1[i & (DHID - 1)];
}

// ---------------------------------------------------------------------------
// K4: h1 += [enc, memvec] @ W1^T   (partial over K-split)
//     grid (128, 2) x 256 threads; 32 outputs x 64 batches per block,
//     K chunk of 1024 per blockIdx.y. Inner loop: packed fma.rn.f32x2.
// ---------------------------------------------------------------------------
__global__ void k4_fc1(const float* __restrict__ enc,
                       const float* __restrict__ W1) {
    __shared__ float2 sh2[32][33];   // batch-pair p = {2p, 2p+1} x k
    __shared__ float  sw[32][33];    // out x k
    int t = threadIdx.x;
    int obase = blockIdx.x * 32;
    int kbeg = blockIdx.y * 1024;
    int ol = t & 31;                 // output lane
    int bg = t >> 5;                 // batch group 0..7 (pairs bg*4..bg*4+3)

    unsigned long long acc2[4] = {0ull, 0ull, 0ull, 0ull};  // (0.f,0.f) packed

    for (int kc = kbeg; kc < kbeg + 1024; kc += 32) {
#pragma unroll
        for (int i = 0; i < 8; i++) {           // 64x32 h tile
            int e = t + i * 256;
            int row = e >> 5, col = e & 31;
            int k = kc + col;
            float v = (k < DD) ? enc[row * DD + k]
                               : g_memvec[row * DD + (k - DD)];
            ((float*)&sh2[row >> 1][col])[row & 1] = v;
        }
#pragma unroll
        for (int i = 0; i < 4; i++) {           // 32x32 W tile
            int e = t + i * 256;
            int row = e >> 5, col = e & 31;
            sw[row][col] = W1[(size_t)(obase + row) * DIN + kc + col];
        }
        __syncthreads();
#pragma unroll
        for (int kk = 0; kk < 32; kk++) {
            float wv = sw[ol][kk];
            unsigned long long w2;
            asm("mov.b64 %0, {%1, %1};" : "=l"(w2) : "f"(wv));
#pragma unroll
            for (int j = 0; j < 4; j++) {
                unsigned long long h2 = *(const unsigned long long*)&sh2[bg * 4 + j][kk];
                asm("fma.rn.f32x2 %0, %1, %2, %0;" : "+l"(acc2[j]) : "l"(h2), "l"(w2));
            }
        }
        __syncthreads();
    }
    int o = obase + ol;
#pragma unroll
    for (int j = 0; j < 4; j++) {
        float lo, hi;
        asm("mov.b64 {%0, %1}, %2;" : "=f"(lo), "=f"(hi) : "l"(acc2[j]));
        int p = bg * 8 + j * 2;
        atomicAdd(&g_h1[(size_t)p * DHID + o], lo);
        atomicAdd(&g_h1[(size_t)(p + 1) * DHID + o], hi);
    }
}

// ---------------------------------------------------------------------------
// K5 init: out[b, o] = b2[o]
// ---------------------------------------------------------------------------
__global__ void k5_init(const float* __restrict__ b2, float* __restrict__ out) {
    int i = blockIdx.x * 256 + threadIdx.x;   // BB*NOUT / 256 = 250 blocks
    out[i] = b2[i % NOUT];
}

// ---------------------------------------------------------------------------
// K5: out += relu(h1) @ W2^T   (partial over K-split; relu fused in h-load)
//     grid (32, 4) x 256 threads; 32 outputs x 64 batches, K chunk 1024.
// ---------------------------------------------------------------------------
__global__ void k5_fc2(const float* __restrict__ W2, float* __restrict__ out) {
    __shared__ float2 sh2[32][33];
    __shared__ float  sw[32][33];
    int t = threadIdx.x;
    int obase = blockIdx.x * 32;
    int kbeg = blockIdx.y * 1024;
    int ol = t & 31;
    int bg = t >> 5;

    unsigned long long acc2[4] = {0ull, 0ull, 0ull, 0ull};

    for (int kc = kbeg; kc < kbeg + 1024; kc += 32) {
#pragma unroll
        for (int i = 0; i < 8; i++) {
            int e = t + i * 256;
            int row = e >> 5, col = e & 31;
            float v = fmaxf(g_h1[(size_t)row * DHID + kc + col], 0.f);  // relu
            ((float*)&sh2[row >> 1][col])[row & 1] = v;
        }
#pragma unroll
        for (int i = 0; i < 4; i++) {
            int e = t + i * 256;
            int row = e >> 5, col = e & 31;
            int o = obase + row;
            sw[row][col] = (o < NOUT) ? W2[(size_t)o * DHID + kc + col] : 0.f;
        }
        __syncthreads();
#pragma unroll
        for (int kk = 0; kk < 32; kk++) {
            float wv = sw[ol][kk];
            unsigned long long w2;
            asm("mov.b64 %0, {%1, %1};" : "=l"(w2) : "f"(wv));
#pragma unroll
            for (int j = 0; j < 4; j++) {
                unsigned long long h2 = *(const unsigned long long*)&sh2[bg * 4 + j][kk];
                asm("fma.rn.f32x2 %0, %1, %2, %0;" : "+l"(acc2[j]) : "l"(h2), "l"(w2));
            }
        }
        __syncthreads();
    }
    int o = obase + ol;
    if (o < NOUT) {
#pragma unroll
        for (int j = 0; j < 4; j++) {
            float lo, hi;
            asm("mov.b64 {%0, %1}, %2;" : "=f"(lo), "=f"(hi) : "l"(acc2[j]));
            int p = bg * 8 + j * 2;
            atomicAdd(&out[(size_t)p * NOUT + o], lo);
            atomicAdd(&out[(size_t)(p + 1) * NOUT + o], hi);
        }
    }
}

// ---------------------------------------------------------------------------
extern "C" void kernel_launch(void* const* d_in, const int* in_sizes, int n_in,
                              void* d_out, int out_size) {
    const float* enc = (const float*)d_in[0];   // [64,1024]
    const float* mem = (const float*)d_in[1];   // [64,4096,1024]
    const float* W1  = (const float*)d_in[2];   // [4096,2048]
    const float* b1  = (const float*)d_in[3];   // [4096]
    const float* W2  = (const float*)d_in[4];   // [1000,4096]
    const float* b2  = (const float*)d_in[5];   // [1000]
    float* out = (float*)d_out;                 // [64,1000]

    k0_norm_enc<<<BB, 256>>>(enc);
    k1_scores<<<(BB * NN) / 16, 256>>>(mem);
    k2_sparsemax<<<BB, 512>>>();
    k3_weighted_sum<<<dim3(BB, 16), 256>>>(mem);
    k4_init<<<(BB * DHID) / 256, 256>>>(b1);
    k4_fc1<<<dim3(DHID / 32, 2), 256>>>(enc, W1);
    k5_init<<<(BB * NOUT) / 256, 256>>>(b2, out);
    k5_fc2<<<dim3(32, 4), 256>>>(W2, out);
}

// round 3
// speedup vs baseline: 1.9598x; 1.0652x over previous
#include <cuda_runtime.h>
#include <math.h>

#define BB   64
#define NN   4096
#define DD   1024
#define DIN  2048
#define DHID 4096
#define NOUT 1000

// ---- scratch (device globals; no allocation allowed) ----
__device__ float g_xn[BB * DD];        // normalized encoder
__device__ float g_z[BB * NN];         // sparsemax input scores
__device__ int   g_nzidx[BB * NN];     // compacted support indices
__device__ float g_nzw[BB * NN];       // compacted weights
__device__ int   g_nnz[BB];
__device__ float g_memvec[BB * DD];    // weighted memory readout (atomic acc)
__device__ float g_h1[BB * DHID];      // hidden pre-activations (atomic acc)

// ---------------------------------------------------------------------------
// K0: xn = enc / max(||enc||, 1e-6)   (64 blocks x 256)
// ---------------------------------------------------------------------------
__global__ void k0_norm_enc(const float* __restrict__ enc) {
    int b = blockIdx.x;
    __shared__ float red[256];
    float ssq = 0.f;
    for (int i = threadIdx.x; i < DD; i += 256) {
        float v = enc[b * DD + i];
        ssq = fmaf(v, v, ssq);
    }
    red[threadIdx.x] = ssq;
    __syncthreads();
    for (int s = 128; s > 0; s >>= 1) {
        if (threadIdx.x < s) red[threadIdx.x] += red[threadIdx.x + s];
        __syncthreads();
    }
    float inv = 1.f / fmaxf(sqrtf(red[0]), 1e-6f);
    for (int i = threadIdx.x; i < DD; i += 256)
        g_xn[b * DD + i] = enc[b * DD + i] * inv;
}

// ---------------------------------------------------------------------------
// K1: the 1.07 GB pass. Block = 64 rows of one batch; each warp preloads its
//     xn slice into REGISTERS once and sweeps 8 rows in 4 pairs (streaming
//     __ldcs loads, 8 independent 512B loads in flight per pair).
//     grid = B*N/64 = 4096 blocks x 256 threads
// ---------------------------------------------------------------------------
__global__ void __launch_bounds__(256) k1_scores(const float* __restrict__ mem) {
    int warp = threadIdx.x >> 5, lane = threadIdx.x & 31;
    int rbase = blockIdx.x * 64 + warp * 8;   // 8 rows for this warp
    int b = rbase >> 12;                      // N = 4096, blocks batch-aligned

    const float4* x4 = (const float4*)g_xn + (size_t)b * (DD / 4);
    float4 x[8];
#pragma unroll
    for (int i = 0; i < 8; i++) x[i] = x4[lane + i * 32];

    const float4* mrow = (const float4*)mem + (size_t)rbase * (DD / 4);

#pragma unroll
    for (int rr = 0; rr < 8; rr += 2) {
        const float4* A = mrow + rr * (DD / 4);
        const float4* C = A + (DD / 4);
        float d0 = 0.f, s0 = 0.f, d1 = 0.f, s1 = 0.f;
#pragma unroll
        for (int g = 0; g < 2; g++) {
            float4 a[4], c[4];
#pragma unroll
            for (int i = 0; i < 4; i++) {
                a[i] = __ldcs(&A[lane + (g * 4 + i) * 32]);
                c[i] = __ldcs(&C[lane + (g * 4 + i) * 32]);
            }
#pragma unroll
            for (int i = 0; i < 4; i++) {
                float4 xv = x[g * 4 + i];
                d0 = fmaf(a[i].x, xv.x, fmaf(a[i].y, xv.y, fmaf(a[i].z, xv.z, fmaf(a[i].w, xv.w, d0))));
                s0 = fmaf(a[i].x, a[i].x, fmaf(a[i].y, a[i].y, fmaf(a[i].z, a[i].z, fmaf(a[i].w, a[i].w, s0))));
                d1 = fmaf(c[i].x, xv.x, fmaf(c[i].y, xv.y, fmaf(c[i].z, xv.z, fmaf(c[i].w, xv.w, d1))));
                s1 = fmaf(c[i].x, c[i].x, fmaf(c[i].y, c[i].y, fmaf(c[i].z, c[i].z, fmaf(c[i].w, c[i].w, s1))));
            }
        }
#pragma unroll
        for (int o = 16; o; o >>= 1) {
            d0 += __shfl_xor_sync(0xFFFFFFFFu, d0, o);
            s0 += __shfl_xor_sync(0xFFFFFFFFu, s0, o);
            d1 += __shfl_xor_sync(0xFFFFFFFFu, d1, o);
            s1 += __shfl_xor_sync(0xFFFFFFFFu, s1, o);
        }
        if (lane == 0) {
            g_z[rbase + rr]     = d0 / fmaxf(sqrtf(s0), 1e-6f) - 1.0f;
            g_z[rbase + rr + 1] = d1 / fmaxf(sqrtf(s1), 1e-6f) - 1.0f;
        }
    }
}

// ---------------------------------------------------------------------------
// K2: sparsemax via Michelot fixed point (exact, no sort). Warp-shuffle
//     reductions, warp-0 final reduce. Also zeroes g_memvec for K3's atomics.
//     64 blocks x 512 threads, 8 elems/thread.
// ---------------------------------------------------------------------------
__global__ void k2_sparsemax() {
    int b = blockIdx.x, t = threadIdx.x;
    int lane = t & 31, w = t >> 5;            // 16 warps
    __shared__ float sS[16], sK[16];
    __shared__ float s_tau;
    __shared__ int cnt;

    float loc[8];
#pragma unroll
    for (int i = 0; i < 8; i++) loc[i] = g_z[b * NN + t + i * 512];

    // zero the memvec accumulator (consumed by K3 atomics)
    for (int i = t; i < DD; i += 512) g_memvec[b * DD + i] = 0.f;

    // initial tau = (sum - 1)/N
    float S = 0.f;
#pragma unroll
    for (int i = 0; i < 8; i++) S += loc[i];
#pragma unroll
    for (int o = 16; o; o >>= 1) S += __shfl_xor_sync(0xFFFFFFFFu, S, o);
    if (lane == 0) sS[w] = S;
    __syncthreads();
    if (w == 0) {
        float ss = (lane < 16) ? sS[lane] : 0.f;
#pragma unroll
        for (int o = 8; o; o >>= 1) ss += __shfl_xor_sync(0xFFFFFFFFu, ss, o);
        if (lane == 0) s_tau = (ss - 1.f) / (float)NN;
    }
    __syncthreads();
    float tau = s_tau;

    // Michelot: tau <- (sum_{z>tau} z - 1)/count; monotone non-decreasing.
    for (int it = 0; it < 48; it++) {
        float s = 0.f, k = 0.f;
#pragma unroll
        for (int i = 0; i < 8; i++) {
            float v = loc[i];
            if (v > tau) { s += v; k += 1.f; }
        }
#pragma unroll
        for (int o = 16; o; o >>= 1) {
            s += __shfl_xor_sync(0xFFFFFFFFu, s, o);
            k += __shfl_xor_sync(0xFFFFFFFFu, k, o);
        }
        if (lane == 0) { sS[w] = s; sK[w] = k; }
        __syncthreads();
        if (w == 0) {
            float ss = (lane < 16) ? sS[lane] : 0.f;
            float kk = (lane < 16) ? sK[lane] : 0.f;
#pragma unroll
            for (int o = 8; o; o >>= 1) {
                ss += __shfl_xor_sync(0xFFFFFFFFu, ss, o);
                kk += __shfl_xor_sync(0xFFFFFFFFu, kk, o);
            }
            if (lane == 0) s_tau = (ss - 1.f) / kk;
        }
        __syncthreads();
        float tn = s_tau;
        if (!(tn > tau)) break;   // fixed point (uniform decision via smem)
        tau = tn;
    }

    if (t == 0) cnt = 0;
    __syncthreads();
#pragma unroll
    for (int i = 0; i < 8; i++) {
        float wv = loc[i] - tau;
        if (wv > 0.f) {
            int p = atomicAdd(&cnt, 1);
            g_nzidx[b * NN + p] = t + i * 512;
            g_nzw[b * NN + p] = wv;
        }
    }
    __syncthreads();
    if (t == 0) g_nnz[b] = cnt;
}

// ---------------------------------------------------------------------------
// K3: memvec[b,:] += sum over a contiguous support chunk of w * mem[b,idx,:]
//     grid (64, 16); 4-wide row unroll for MLP=4; atomicAdd accumulation.
// ---------------------------------------------------------------------------
__global__ void k3_weighted_sum(const float* __restrict__ mem) {
    int b = blockIdx.x, s = blockIdx.y, t = threadIdx.x;
    int nnz = g_nnz[b];
    int chunk = (nnz + 15) >> 4;
    int i0 = s * chunk;
    int i1 = min(nnz, i0 + chunk);
    if (i0 >= i1) return;

    const float4* base = (const float4*)mem + (size_t)b * NN * (DD / 4);
    const int*   idxp = &g_nzidx[b * NN];
    const float* wp   = &g_nzw[b * NN];

    float4 acc = make_float4(0.f, 0.f, 0.f, 0.f);
    int i = i0;
    for (; i + 4 <= i1; i += 4) {
        int   j0 = idxp[i],     j1 = idxp[i + 1], j2 = idxp[i + 2], j3 = idxp[i + 3];
        float w0 = wp[i],       w1 = wp[i + 1],   w2 = wp[i + 2],   w3 = wp[i + 3];
        float4 m0 = __ldcs(&base[(size_t)j0 * (DD / 4) + t]);
        float4 m1 = __ldcs(&base[(size_t)j1 * (DD / 4) + t]);
        float4 m2 = __ldcs(&base[(size_t)j2 * (DD / 4) + t]);
        float4 m3 = __ldcs(&base[(size_t)j3 * (DD / 4) + t]);
        acc.x = fmaf(w0, m0.x, fmaf(w1, m1.x, fmaf(w2, m2.x, fmaf(w3, m3.x, acc.x))));
        acc.y = fmaf(w0, m0.y, fmaf(w1, m1.y, fmaf(w2, m2.y, fmaf(w3, m3.y, acc.y))));
        acc.z = fmaf(w0, m0.z, fmaf(w1, m1.z, fmaf(w2, m2.z, fmaf(w3, m3.z, acc.z))));
        acc.w = fmaf(w0, m0.w, fmaf(w1, m1.w, fmaf(w2, m2.w, fmaf(w3, m3.w, acc.w))));
    }
    for (; i < i1; i++) {
        int j = idxp[i];
        float wv = wp[i];
        float4 m = __ldcs(&base[(size_t)j * (DD / 4) + t]);
        acc.x = fmaf(wv, m.x, acc.x);
        acc.y = fmaf(wv, m.y, acc.y);
        acc.z = fmaf(wv, m.z, acc.z);
        acc.w = fmaf(wv, m.w, acc.w);
    }
    float* dst = &g_memvec[b * DD + t * 4];
    atomicAdd(dst + 0, acc.x);
    atomicAdd(dst + 1, acc.y);
    atomicAdd(dst + 2, acc.z);
    atomicAdd(dst + 3, acc.w);
}

// ---------------------------------------------------------------------------
// K4 init: h1[b, o] = b1[o]
// ---------------------------------------------------------------------------
__global__ void k4_init(const float* __restrict__ b1) {
    int i = blockIdx.x * 256 + threadIdx.x;
    g_h1[i] = b1[i & (DHID - 1)];
}

// ---------------------------------------------------------------------------
// K4: h1 += [enc, memvec] @ W1^T   (K-split partials, atomicAdd)
//     Tile: 64 outputs x 64 batches x K-chunk 32. Weights pre-splatted to
//     float2 in smem; inner loop = 2 LDS64(w) + 4 LDS64(h) + 8 FFMA2.
//     grid (DHID/64, 4) x 256 threads.
// ---------------------------------------------------------------------------
__global__ void k4_fc1(const float* __restrict__ enc,
                       const float* __restrict__ W1) {
    __shared__ float2 sw2[64][33];   // [out][k], splatted {w,w}
    __shared__ float2 sh2[32][33];   // [batch-pair][k]
    int t = threadIdx.x;
    int obase = blockIdx.x * 64;
    int kbeg = blockIdx.y * (DIN / 4);
    int ol = t & 31;                 // outputs: obase+ol, obase+32+ol
    int bg = t >> 5;                 // batches bg*8 .. bg*8+7

    unsigned long long accA[4] = {0ull, 0ull, 0ull, 0ull};
    unsigned long long accB[4] = {0ull, 0ull, 0ull, 0ull};

    for (int kc = kbeg; kc < kbeg + DIN / 4; kc += 32) {
#pragma unroll
        for (int i = 0; i < 8; i++) {           // 64x32 h tile
            int e = t + i * 256;
            int row = e >> 5, col = e & 31;
            int k = kc + col;
            float v = (k < DD) ? enc[row * DD + k]
                               : g_memvec[row * DD + (k - DD)];
            ((float*)&sh2[row >> 1][col])[row & 1] = v;
        }
#pragma unroll
        for (int i = 0; i < 8; i++) {           // 64x32 W tile, splat
            int e = t + i * 256;
            int row = e >> 5, col = e & 31;
            float wv = W1[(size_t)(obase + row) * DIN + kc + col];
            sw2[row][col] = make_float2(wv, wv);
        }
        __syncthreads();
#pragma unroll
        for (int kk = 0; kk < 32; kk++) {
            unsigned long long wa = *(const unsigned long long*)&sw2[ol][kk];
            unsigned long long wb = *(const unsigned long long*)&sw2[ol + 32][kk];
#pragma unroll
            for (int j = 0; j < 4; j++) {
                unsigned long long h2 = *(const unsigned long long*)&sh2[bg * 4 + j][kk];
                asm("fma.rn.f32x2 %0, %1, %2, %0;" : "+l"(accA[j]) : "l"(h2), "l"(wa));
                asm("fma.rn.f32x2 %0, %1, %2, %0;" : "+l"(accB[j]) : "l"(h2), "l"(wb));
            }
        }
        __syncthreads();
    }
    int o0 = obase + ol, o1 = obase + 32 + ol;
#pragma unroll
    for (int j = 0; j < 4; j++) {
        float lo, hi;
        int p = bg * 8 + j * 2;
        asm("mov.b64 {%0, %1}, %2;" : "=f"(lo), "=f"(hi) : "l"(accA[j]));
        atomicAdd(&g_h1[(size_t)p * DHID + o0], lo);
        atomicAdd(&g_h1[(size_t)(p + 1) * DHID + o0], hi);
        asm("mov.b64 {%0, %1}, %2;" : "=f"(lo), "=f"(hi) : "l"(accB[j]));
        atomicAdd(&g_h1[(size_t)p * DHID + o1], lo);
        atomicAdd(&g_h1[(size_t)(p + 1) * DHID + o1], hi);
    }
}

// ---------------------------------------------------------------------------
// K5 init: out[b, o] = b2[o]
// ---------------------------------------------------------------------------
__global__ void k5_init(const float* __restrict__ b2, float* __restrict__ out) {
    int i = blockIdx.x * 256 + threadIdx.x;
    if (i < BB * NOUT) out[i] = b2[i % NOUT];
}

// ---------------------------------------------------------------------------
// K5: out += relu(h1) @ W2^T   (K-split partials; relu fused in h-load)
//     Same 64x64 tile as K4, with output masking (NOUT=1000).
//     grid (16, 8) x 256 threads.
// ---------------------------------------------------------------------------
__global__ void k5_fc2(const float* __restrict__ W2, float* __restrict__ out) {
    __shared__ float2 sw2[64][33];
    __shared__ float2 sh2[32][33];
    int t = threadIdx.x;
    int obase = blockIdx.x * 64;
    int kbeg = blockIdx.y * (DHID / 8);
    int ol = t & 31;
    int bg = t >> 5;

    unsigned long long accA[4] = {0ull, 0ull, 0ull, 0ull};
    unsigned long long accB[4] = {0ull, 0ull, 0ull, 0ull};

    for (int kc = kbeg; kc < kbeg + DHID / 8; kc += 32) {
#pragma unroll
        for (int i = 0; i < 8; i++) {
            int e = t + i * 256;
            int row = e >> 5, col = e & 31;
            float v = fmaxf(g_h1[(size_t)row * DHID + kc + col], 0.f);  // relu
            ((float*)&sh2[row >> 1][col])[row & 1] = v;
        }
#pragma unroll
        for (int i = 0; i < 8; i++) {
            int e = t + i * 256;
            int row = e >> 5, col = e & 31;
            int o = obase + row;
            float wv = (o < NOUT) ? W2[(size_t)o * DHID + kc + col] : 0.f;
            sw2[row][col] = make_float2(wv, wv);
        }
        __syncthreads();
#pragma unroll
        for (int kk = 0; kk < 32; kk++) {
            unsigned long long wa = *(const unsigned long long*)&sw2[ol][kk];
            unsigned long long wb = *(const unsigned long long*)&sw2[ol + 32][kk];
#pragma unroll
            for (int j = 0; j < 4; j++) {
                unsigned long long h2 = *(const unsigned long long*)&sh2[bg * 4 + j][kk];
                asm("fma.rn.f32x2 %0, %1, %2, %0;" : "+l"(accA[j]) : "l"(h2), "l"(wa));
                asm("fma.rn.f32x2 %0, %1, %2, %0;" : "+l"(accB[j]) : "l"(h2), "l"(wb));
            }
        }
        __syncthreads();
    }
    int o0 = obase + ol, o1 = obase + 32 + ol;
#pragma unroll
    for (int j = 0; j < 4; j++) {
        float lo, hi;
        int p = bg * 8 + j * 2;
        if (o0 < NOUT) {
            asm("mov.b64 {%0, %1}, %2;" : "=f"(lo), "=f"(hi) : "l"(accA[j]));
            atomicAdd(&out[(size_t)p * NOUT + o0], lo);
            atomicAdd(&out[(size_t)(p + 1) * NOUT + o0], hi);
        }
        if (o1 < NOUT) {
            asm("mov.b64 {%0, %1}, %2;" : "=f"(lo), "=f"(hi) : "l"(accB[j]));
            atomicAdd(&out[(size_t)p * NOUT + o1], lo);
            atomicAdd(&out[(size_t)(p + 1) * NOUT + o1], hi);
        }
    }
}

// ---------------------------------------------------------------------------
extern "C" void kernel_launch(void* const* d_in, const int* in_sizes, int n_in,
                              void* d_out, int out_size) {
    const float* enc = (const float*)d_in[0];   // [64,1024]
    const float* mem = (const float*)d_in[1];   // [64,4096,1024]
    const float* W1  = (const float*)d_in[2];   // [4096,2048]
    const float* b1  = (const float*)d_in[3];   // [4096]
    const float* W2  = (const float*)d_in[4];   // [1000,4096]
    const float* b2  = (const float*)d_in[5];   // [1000]
    float* out = (float*)d_out;                 // [64,1000]

    k0_norm_enc<<<BB, 256>>>(enc);
    k1_scores<<<(BB * NN) / 64, 256>>>(mem);
    k2_sparsemax<<<BB, 512>>>();
    k3_weighted_sum<<<dim3(BB, 16), 256>>>(mem);
    k4_init<<<(BB * DHID) / 256, 256>>>(b1);
    k4_fc1<<<dim3(DHID / 64, 4), 256>>>(enc, W1);
    k5_init<<<(BB * NOUT + 255) / 256, 256>>>(b2, out);
    k5_fc2<<<dim3(16, 8), 256>>>(W2, out);
}